// round 16
// baseline (speedup 1.0000x reference)
#include <cuda_runtime.h>
#include <math.h>

#define BB 4
#define NN 16384
#define HH 8
#define SPLITS 32
#define KCT 64
#define OCT 128
#define L2_10K 0.4152410118609203f

typedef unsigned long long u64;
typedef unsigned int u32;
typedef unsigned short ush;

__device__ __forceinline__ u64 pk2(float a, float b) {
    u64 r;
    asm("mov.b64 %0, {%1, %2};" : "=l"(r)
        : "r"(__float_as_uint(a)), "r"(__float_as_uint(b)));
    return r;
}
__device__ __forceinline__ float2 up2(u64 a) {
    unsigned int lo, hi;
    asm("mov.b64 {%0, %1}, %2;" : "=r"(lo), "=r"(hi) : "l"(a));
    float2 r; r.x = __uint_as_float(lo); r.y = __uint_as_float(hi);
    return r;
}
__device__ __forceinline__ void fma2(u64& d, u64 a, u64 b) {
    asm("fma.rn.f32x2 %0, %1, %2, %0;" : "+l"(d) : "l"(a), "l"(b));
}
__device__ __forceinline__ u64 mul2(u64 a, u64 b) {
    u64 r; asm("mul.rn.f32x2 %0, %1, %2;" : "=l"(r) : "l"(a), "l"(b)); return r;
}

// bf16 helpers
__device__ __forceinline__ u32 cvt2(float hi, float lo) {
    u32 d; asm("cvt.rn.bf16x2.f32 %0, %1, %2;" : "=r"(d) : "f"(hi), "f"(lo));
    return d;
}
__device__ __forceinline__ float blo(u32 h) { return __uint_as_float(h << 16); }
__device__ __forceinline__ float bhi(u32 h) { return __uint_as_float(h & 0xffff0000u); }
__device__ __forceinline__ void split2(float a, float b, u32& h, u32& l) {
    h = cvt2(b, a);
    l = cvt2(b - bhi(h), a - blo(h));
}
__device__ __forceinline__ u32 smaddr(const void* p) {
    u32 r;
    asm("{ .reg .u64 t; cvta.to.shared.u64 t, %1; cvt.u32.u64 %0, t; }" : "=r"(r) : "l"(p));
    return r;
}
__device__ __forceinline__ void ldsm4(u32* r, u32 a) {
    asm volatile("ldmatrix.sync.aligned.m8n8.x4.shared.b16 {%0,%1,%2,%3}, [%4];"
        : "=r"(r[0]), "=r"(r[1]), "=r"(r[2]), "=r"(r[3]) : "r"(a));
}
__device__ __forceinline__ void ldsm4t(u32* r, u32 a) {
    asm volatile("ldmatrix.sync.aligned.m8n8.x4.trans.shared.b16 {%0,%1,%2,%3}, [%4];"
        : "=r"(r[0]), "=r"(r[1]), "=r"(r[2]), "=r"(r[3]) : "r"(a));
}
__device__ __forceinline__ void hmma(float* c, const u32* a, const u32* b) {
    asm volatile(
        "mma.sync.aligned.m16n8k16.row.col.f32.bf16.bf16.f32 "
        "{%0,%1,%2,%3}, {%4,%5,%6,%7}, {%8,%9}, {%0,%1,%2,%3};"
        : "+f"(c[0]), "+f"(c[1]), "+f"(c[2]), "+f"(c[3])
        : "r"(a[0]), "r"(a[1]), "r"(a[2]), "r"(a[3]), "r"(b[0]), "r"(b[1]));
}

// scratch
__device__ float g_kv_part[BB * HH * SPLITS * 64 * 64];
__device__ u32   g_Mh[BB * HH * 64 * 32];
__device__ u32   g_Ml[BB * HH * 64 * 32];
__device__ float g_tabc[BB * NN * 32];
__device__ float g_tabs[BB * NN * 32];

// ============== tab kernel (fast MUFU sincos) ==============
__global__ __launch_bounds__(256)
void tab_kernel(const float* __restrict__ pos)
{
    int idx = blockIdx.x * 256 + threadIdx.x;
    float f = pos[idx >> 5] * 64.f * exp2f(-(float)(idx & 31) * L2_10K);
    float s_, c_;
    __sincosf(f, &s_, &c_);
    g_tabc[idx] = c_;
    g_tabs[idx] = s_;
}

// ============== kv kernel: bf16 mma, 3-pass split (8 chunks of 64) ==============
// smem halves: xk hi/lo [64*72]x2 (x, then k) | v hi/lo [64*72]x2 |
//              W hi [2][64*72] | W lo [2][64*72]  = 36864 halves = 73728 B
__global__ __launch_bounds__(256, 2)
void kv_kernel(const float* __restrict__ x,
               const float* __restrict__ Wk, const float* __restrict__ Wv)
{
    extern __shared__ __align__(16) ush sh[];
    ush* xkh = sh;              // 4608 halves
    ush* xkl = sh + 4608;
    ush* vhs = sh + 9216;
    ush* vls = sh + 13824;
    ush* whb = sh + 18432;      // [sel][64*72]
    ush* wlb = sh + 27648;

    const int tid = threadIdx.x;
    const int b = blockIdx.z, h = blockIdx.y, s = blockIdx.x;
    const int w = tid >> 5, lane = tid & 31;
    const int g = lane >> 2, tc4 = lane & 3;
    const int lr = lane & 15, lc = (lane >> 4) * 8;
    const bool kwarp = (w < 4);
    const int mb = w & 3, rb = mb * 16;
    const int md = w & 3, nhalf = w >> 2;

    // stage Wk/Wv split-bf16
    #pragma unroll
    for (int r = 0; r < 16; r++) {
        int p = tid + r * 256;            // [0,4096) pairs
        int sel = p >> 11;
        int q = p & 2047;
        int i = q >> 5, op = (q & 31) * 2;
        const float* Ws = sel ? Wv : Wk;
        float2 wv2 = *(const float2*)&Ws[i * 512 + h * 64 + op];
        u32 hh, ll;
        split2(wv2.x, wv2.y, hh, ll);
        *(u32*)&whb[sel * 4608 + i * 72 + op] = hh;
        *(u32*)&wlb[sel * 4608 + i * 72 + op] = ll;
    }

    const ush* WH = whb + (kwarp ? 0 : 4608);
    const ush* WL = wlb + (kwarp ? 0 : 4608);
    ush* DH = kwarp ? xkh : vhs;
    ush* DL = kwarp ? xkl : vls;

    float kvc[4][4];
    #pragma unroll
    for (int i = 0; i < 4; i++)
        #pragma unroll
        for (int e = 0; e < 4; e++) kvc[i][e] = 0.f;

    const int tpb = NN / SPLITS;          // 512 tokens per block
    #pragma unroll 1
    for (int c = 0; c < tpb / KCT; c++) { // 8 chunks of 64 tokens
        const int tbase = s * tpb + c * KCT;
        __syncthreads();     // prior GEMM2 reads of xk/v done (also covers W staging)

        // stage x split-bf16 (64 tokens)
        const float* xg = x + ((size_t)b * NN + tbase) * 64;
        #pragma unroll
        for (int r = 0; r < 8; r++) {
            int p = tid + r * 256;        // [0,2048) pairs
            int t = p >> 5, ip = (p & 31) * 2;
            float2 v = *(const float2*)&xg[t * 64 + ip];
            u32 hh, ll;
            split2(v.x, v.y, hh, ll);
            *(u32*)&xkh[t * 72 + ip] = hh;
            *(u32*)&xkl[t * 72 + ip] = ll;
        }
        __syncthreads();

        // GEMM1: proj 16 rows x 64 cols per warp (k or v), 3-pass
        float pc[8][4];
        #pragma unroll
        for (int nb = 0; nb < 8; nb++)
            #pragma unroll
            for (int e = 0; e < 4; e++) pc[nb][e] = 0.f;

        #pragma unroll
        for (int kb = 0; kb < 4; kb++) {
            u32 ah[4], al[4];
            ldsm4(ah, smaddr(&xkh[(rb + lr) * 72 + kb * 16 + lc]));
            ldsm4(al, smaddr(&xkl[(rb + lr) * 72 + kb * 16 + lc]));
            #pragma unroll
            for (int nl = 0; nl < 4; nl++) {
                u32 bh[4], bl[4];
                ldsm4t(bh, smaddr(&WH[(kb * 16 + lr) * 72 + nl * 16 + lc]));
                ldsm4t(bl, smaddr(&WL[(kb * 16 + lr) * 72 + nl * 16 + lc]));
                hmma(pc[2 * nl],     ah, &bh[0]);
                hmma(pc[2 * nl],     al, &bh[0]);
                hmma(pc[2 * nl],     ah, &bl[0]);
                hmma(pc[2 * nl + 1], ah, &bh[2]);
                hmma(pc[2 * nl + 1], al, &bh[2]);
                hmma(pc[2 * nl + 1], ah, &bl[2]);
            }
        }
        __syncthreads();     // x reads done before overwrite with k

        // LayerNorm: rows rb+g (elems 0,1) and rb+g+8 (elems 2,3)
        float s1a = 0.f, s2a = 0.f, s1b = 0.f, s2b = 0.f;
        #pragma unroll
        for (int nb = 0; nb < 8; nb++) {
            s1a += pc[nb][0] + pc[nb][1];
            s2a += pc[nb][0] * pc[nb][0] + pc[nb][1] * pc[nb][1];
            s1b += pc[nb][2] + pc[nb][3];
            s2b += pc[nb][2] * pc[nb][2] + pc[nb][3] * pc[nb][3];
        }
        #pragma unroll
        for (int m = 1; m < 4; m <<= 1) {
            s1a += __shfl_xor_sync(0xffffffffu, s1a, m);
            s2a += __shfl_xor_sync(0xffffffffu, s2a, m);
            s1b += __shfl_xor_sync(0xffffffffu, s1b, m);
            s2b += __shfl_xor_sync(0xffffffffu, s2b, m);
        }
        float ma = s1a * (1.f / 64.f);
        float ra = rsqrtf(fmaxf(s2a * (1.f / 64.f) - ma * ma, 0.f) + 1e-5f);
        float mb_ = s1b * (1.f / 64.f);
        float rbn = rsqrtf(fmaxf(s2b * (1.f / 64.f) - mb_ * mb_, 0.f) + 1e-5f);
        #pragma unroll
        for (int nb = 0; nb < 8; nb++) {
            pc[nb][0] = (pc[nb][0] - ma) * ra;
            pc[nb][1] = (pc[nb][1] - ma) * ra;
            pc[nb][2] = (pc[nb][2] - mb_) * rbn;
            pc[nb][3] = (pc[nb][3] - mb_) * rbn;
        }

        if (kwarp) {   // RoPE on k: col c <-> c+32 == nb <-> nb+4
            const size_t tr = (size_t)b * NN + tbase + rb + g;
            const float* tcb = &g_tabc[tr * 32 + 2 * tc4];
            const float* tsb = &g_tabs[tr * 32 + 2 * tc4];
            #pragma unroll
            for (int nb = 0; nb < 4; nb++) {
                float2 c0 = *(const float2*)(tcb + 8 * nb);
                float2 c1 = *(const float2*)(tcb + 256 + 8 * nb);
                float2 s0 = *(const float2*)(tsb + 8 * nb);
                float2 s1 = *(const float2*)(tsb + 256 + 8 * nb);
                float cs[4] = { c0.x, c0.y, c1.x, c1.y };
                float sn[4] = { s0.x, s0.y, s1.x, s1.y };
                #pragma unroll
                for (int e = 0; e < 4; e++) {
                    float lo = pc[nb][e], hi = pc[nb + 4][e];
                    pc[nb][e]     = lo * cs[e] - hi * sn[e];
                    pc[nb + 4][e] = hi * cs[e] + lo * sn[e];
                }
            }
        }

        // store split-bf16 k/v
        #pragma unroll
        for (int nb = 0; nb < 8; nb++) {
            u32 hh, ll;
            split2(pc[nb][0], pc[nb][1], hh, ll);
            *(u32*)&DH[(rb + g) * 72 + 8 * nb + 2 * tc4] = hh;
            *(u32*)&DL[(rb + g) * 72 + 8 * nb + 2 * tc4] = ll;
            split2(pc[nb][2], pc[nb][3], hh, ll);
            *(u32*)&DH[(rb + g + 8) * 72 + 8 * nb + 2 * tc4] = hh;
            *(u32*)&DL[(rb + g + 8) * 72 + 8 * nb + 2 * tc4] = ll;
        }
        __syncthreads();

        // GEMM2: kv[d][e] += k^T v  (A via trans from [t][d]: perm {0,2,1,3})
        #pragma unroll
        for (int kt = 0; kt < 4; kt++) {
            u32 t0[4], t1[4];
            ldsm4t(t0, smaddr(&xkh[(kt * 16 + lr) * 72 + md * 16 + lc]));
            ldsm4t(t1, smaddr(&xkl[(kt * 16 + lr) * 72 + md * 16 + lc]));
            u32 ah[4] = { t0[0], t0[2], t0[1], t0[3] };
            u32 al[4] = { t1[0], t1[2], t1[1], t1[3] };
            #pragma unroll
            for (int nl = 0; nl < 2; nl++) {
                u32 bh[4], bl[4];
                ldsm4t(bh, smaddr(&vhs[(kt * 16 + lr) * 72 + nhalf * 32 + nl * 16 + lc]));
                ldsm4t(bl, smaddr(&vls[(kt * 16 + lr) * 72 + nhalf * 32 + nl * 16 + lc]));
                hmma(kvc[2 * nl],     ah, &bh[0]);
                hmma(kvc[2 * nl],     al, &bh[0]);
                hmma(kvc[2 * nl],     ah, &bl[0]);
                hmma(kvc[2 * nl + 1], ah, &bh[2]);
                hmma(kvc[2 * nl + 1], al, &bh[2]);
                hmma(kvc[2 * nl + 1], ah, &bl[2]);
            }
        }
    }

    // epilogue: fp32 partial kv
    float* dst = g_kv_part + ((size_t)((b * HH + h) * SPLITS + s)) * 4096;
    const int d0 = md * 16 + g;
    #pragma unroll
    for (int nb = 0; nb < 4; nb++) {
        int col = nhalf * 32 + 8 * nb + 2 * tc4;
        float2 v0 = { kvc[nb][0], kvc[nb][1] };
        float2 v1 = { kvc[nb][2], kvc[nb][3] };
        *(float2*)&dst[d0 * 64 + col]       = v0;
        *(float2*)&dst[(d0 + 8) * 64 + col] = v1;
    }
}

// ============== m kernel: reduce + M=(kv@Wo)/N, emit bf16 hi/lo ==============
__global__ __launch_bounds__(256, 1)
void m_kernel(const float* __restrict__ Wo)
{
    __shared__ float kvs[64 * 66];
    __shared__ float wo[64 * 64];
    const int tid = threadIdx.x;
    const int h = blockIdx.x, b = blockIdx.y;
    const float* src = g_kv_part + (size_t)(b * HH + h) * SPLITS * 4096;

    #pragma unroll
    for (int r = 0; r < 16; r++) {
        int idx = tid + r * 256;
        float acc = 0.f;
        #pragma unroll 4
        for (int s = 0; s < SPLITS; s++) acc += src[s * 4096 + idx];
        int i = idx >> 6, j = idx & 63;
        kvs[i * 66 + j] = acc;
        wo[idx] = Wo[(h * 64 + i) * 64 + j];
    }
    __syncthreads();

    const int i0 = (tid >> 3) * 2;
    const int d0 = (tid & 7) * 8;
    u64 a[2][4];
    #pragma unroll
    for (int ij = 0; ij < 2; ij++)
        #pragma unroll
        for (int p = 0; p < 4; p++) a[ij][p] = 0ull;

    #pragma unroll 8
    for (int j = 0; j < 64; j++) {
        float k0 = kvs[i0 * 66 + j], k1 = kvs[(i0 + 1) * 66 + j];
        u64 p0 = pk2(k0, k0), p1 = pk2(k1, k1);
        ulonglong2 w0 = *(const ulonglong2*)&wo[j * 64 + d0];
        ulonglong2 w1 = *(const ulonglong2*)&wo[j * 64 + d0 + 4];
        u64 wp[4] = { w0.x, w0.y, w1.x, w1.y };
        #pragma unroll
        for (int p = 0; p < 4; p++) {
            fma2(a[0][p], p0, wp[p]);
            fma2(a[1][p], p1, wp[p]);
        }
    }
    const float sc = 1.f / (float)NN;
    const u64 sc2 = pk2(sc, sc);
    const int mbase = (b * HH + h) * 64 * 32;
    #pragma unroll
    for (int ij = 0; ij < 2; ij++)
        #pragma unroll
        for (int p = 0; p < 4; p++) {
            float2 v = up2(mul2(a[ij][p], sc2));
            u32 hh, ll;
            split2(v.x, v.y, hh, ll);
            int idx = mbase + (i0 + ij) * 32 + (d0 >> 1) + p;
            g_Mh[idx] = hh;
            g_Ml[idx] = ll;
        }
}

// ============== out kernel: bf16 mma, 3-pass, x-fragments hoisted ==============
__global__ __launch_bounds__(256, 2)
void out_kernel(const float* __restrict__ x,
                const float* __restrict__ Wq, float* __restrict__ out)
{
    extern __shared__ __align__(16) ush sh[];
    ush* xbh = sh;
    ush* xbl = xbh + 128 * 72;
    ush* whs = xbl + 128 * 72;
    ush* wls = whs + 64 * 72;
    ush* mhs = wls + 64 * 72;
    ush* mls = mhs + 64 * 72;

    const int tid = threadIdx.x;
    const int b = blockIdx.y;
    const int tbase = blockIdx.x * OCT;
    const int w = tid >> 5, lane = tid & 31;
    const int g = lane >> 2, tc4 = lane & 3;
    const int rb = w * 16;
    const int lr = lane & 15, lc = (lane >> 4) * 8;

    const float* xg = x + ((size_t)b * NN + tbase) * 64;
    #pragma unroll
    for (int r = 0; r < 16; r++) {
        int p = tid + r * 256;
        int t = p >> 5, ip = (p & 31) * 2;
        float2 v = *(const float2*)&xg[t * 64 + ip];
        u32 hh, ll;
        split2(v.x, v.y, hh, ll);
        *(u32*)&xbh[t * 72 + ip] = hh;
        *(u32*)&xbl[t * 72 + ip] = ll;
    }
    __syncthreads();

    // hoist x A-fragments (head-invariant)
    u32 xah[4][4], xal[4][4];
    #pragma unroll
    for (int kb = 0; kb < 4; kb++) {
        ldsm4(xah[kb], smaddr(&xbh[(rb + lr) * 72 + kb * 16 + lc]));
        ldsm4(xal[kb], smaddr(&xbl[(rb + lr) * 72 + kb * 16 + lc]));
    }

    float oc[8][4];
    #pragma unroll
    for (int nb = 0; nb < 8; nb++)
        #pragma unroll
        for (int e = 0; e < 4; e++) oc[nb][e] = 0.f;

    const size_t trow = (size_t)b * NN + tbase + rb + g;
    const float* tcb = &g_tabc[trow * 32 + 2 * tc4];
    const float* tsb = &g_tabs[trow * 32 + 2 * tc4];

    #pragma unroll 1
    for (int hh8 = 0; hh8 < HH; hh8++) {
        const int mbase = (b * HH + hh8) * 64 * 32;
        #pragma unroll
        for (int r = 0; r < 8; r++) {
            int p = tid + r * 256;
            int i = p >> 5, op = (p & 31) * 2;
            float2 wv = *(const float2*)&Wq[i * 512 + hh8 * 64 + op];
            u32 whv, wlv;
            split2(wv.x, wv.y, whv, wlv);
            *(u32*)&whs[i * 72 + op] = whv;
            *(u32*)&wls[i * 72 + op] = wlv;
            *(u32*)&mhs[i * 72 + op] = g_Mh[mbase + i * 32 + (op >> 1)];
            *(u32*)&mls[i * 72 + op] = g_Ml[mbase + i * 32 + (op >> 1)];
        }
        __syncthreads();

        float qc[8][4];
        #pragma unroll
        for (int nb = 0; nb < 8; nb++)
            #pragma unroll
            for (int e = 0; e < 4; e++) qc[nb][e] = 0.f;

        #pragma unroll
        for (int kb = 0; kb < 4; kb++) {
            #pragma unroll
            for (int nb2 = 0; nb2 < 4; nb2++) {
                u32 bh[4], bl[4];
                ldsm4t(bh, smaddr(&whs[(kb * 16 + lr) * 72 + nb2 * 16 + lc]));
                ldsm4t(bl, smaddr(&wls[(kb * 16 + lr) * 72 + nb2 * 16 + lc]));
                hmma(qc[2 * nb2],     xah[kb], &bh[0]);
                hmma(qc[2 * nb2],     xal[kb], &bh[0]);
                hmma(qc[2 * nb2],     xah[kb], &bl[0]);
                hmma(qc[2 * nb2 + 1], xah[kb], &bh[2]);
                hmma(qc[2 * nb2 + 1], xal[kb], &bh[2]);
                hmma(qc[2 * nb2 + 1], xah[kb], &bl[2]);
            }
        }

        #pragma unroll
        for (int nb = 0; nb < 4; nb++) {
            float2 c0 = *(const float2*)(tcb + 8 * nb);
            float2 c1 = *(const float2*)(tcb + 256 + 8 * nb);
            float2 s0 = *(const float2*)(tsb + 8 * nb);
            float2 s1 = *(const float2*)(tsb + 256 + 8 * nb);
            float cs[4] = { c0.x, c0.y, c1.x, c1.y };
            float sn[4] = { s0.x, s0.y, s1.x, s1.y };
            #pragma unroll
            for (int e = 0; e < 4; e++) {
                float lo = qc[nb][e], hi = qc[nb + 4][e];
                qc[nb][e]     = lo * cs[e] - hi * sn[e];
                qc[nb + 4][e] = hi * cs[e] + lo * sn[e];
            }
        }

        #pragma unroll
        for (int kb = 0; kb < 4; kb++) {
            u32 qah[4], qal[4];
            split2(qc[2 * kb][0],     qc[2 * kb][1],     qah[0], qal[0]);
            split2(qc[2 * kb][2],     qc[2 * kb][3],     qah[1], qal[1]);
            split2(qc[2 * kb + 1][0], qc[2 * kb + 1][1], qah[2], qal[2]);
            split2(qc[2 * kb + 1][2], qc[2 * kb + 1][3], qah[3], qal[3]);
            #pragma unroll
            for (int nb2 = 0; nb2 < 4; nb2++) {
                u32 bh[4], bl[4];
                ldsm4t(bh, smaddr(&mhs[(kb * 16 + lr) * 72 + nb2 * 16 + lc]));
                ldsm4t(bl, smaddr(&mls[(kb * 16 + lr) * 72 + nb2 * 16 + lc]));
                hmma(oc[2 * nb2],     qah, &bh[0]);
                hmma(oc[2 * nb2],     qal, &bh[0]);
                hmma(oc[2 * nb2],     qah, &bl[0]);
                hmma(oc[2 * nb2 + 1], qah, &bh[2]);
                hmma(oc[2 * nb2 + 1], qal, &bh[2]);
                hmma(oc[2 * nb2 + 1], qah, &bl[2]);
            }
        }
        __syncthreads();
    }

    float* outg = out + ((size_t)b * NN + tbase + rb) * 64;
    #pragma unroll
    for (int nb = 0; nb < 8; nb++) {
        float2 v0 = { oc[nb][0], oc[nb][1] };
        float2 v1 = { oc[nb][2], oc[nb][3] };
        *(float2*)&outg[g * 64 + 8 * nb + 2 * tc4]       = v0;
        *(float2*)&outg[(g + 8) * 64 + 8 * nb + 2 * tc4] = v1;
    }
}

// =====================================================================
extern "C" void kernel_launch(void* const* d_in, const int* in_sizes, int n_in,
                              void* d_out, int out_size)
{
    const float* x   = (const float*)d_in[0];
    const float* pos = (const float*)d_in[1];
    const float* Wq  = (const float*)d_in[2];
    const float* Wk  = (const float*)d_in[3];
    const float* Wv  = (const float*)d_in[4];
    const float* Wo  = (const float*)d_in[5];
    float* out = (float*)d_out;

    const int SMEM_KV  = 36864 * 2;                         // 73728 B
    const int SMEM_OUT = (2 * 128 * 72 + 4 * 64 * 72) * 2;  // 73728 B
    cudaFuncSetAttribute(kv_kernel,  cudaFuncAttributeMaxDynamicSharedMemorySize, SMEM_KV);
    cudaFuncSetAttribute(out_kernel, cudaFuncAttributeMaxDynamicSharedMemorySize, SMEM_OUT);

    tab_kernel<<<BB * NN * 32 / 256, 256>>>(pos);
    kv_kernel<<<dim3(SPLITS, HH, BB), 256, SMEM_KV>>>(x, Wk, Wv);
    m_kernel<<<dim3(HH, BB), 256>>>(Wo);
    out_kernel<<<dim3(NN / OCT, BB), 256, SMEM_OUT>>>(x, Wq, out);
}